// round 6
// baseline (speedup 1.0000x reference)
#include <cuda_runtime.h>
#include <cuda_bf16.h>
#include <cstdint>
#include <cstddef>

#define N_NODES 50000
#define N_EDGES 800000
#define SCAN_B  256
#define SCAN_NB ((N_NODES + SCAN_B - 1) / SCAN_B)

// Scratch (allocation-free rule: __device__ globals)
__device__ float g_S[(size_t)N_NODES * 128];   // support = h @ W
__device__ float g_A[(size_t)N_NODES * 128];   // aggregation target / next-layer input
__device__ int   g_off[N_NODES + 1];           // CSR row offsets (by dst)
__device__ int   g_cur[N_NODES];               // histogram counts / running cursors
__device__ int   g_part[SCAN_NB];              // scan block partials
__device__ int   g_src_s[N_EDGES];             // src sorted by dst
__device__ float g_val_s[N_EDGES];             // val sorted by dst

// ---------------------------------------------------------------------------
// GEMM: C[N, DOUT] = act(H)[N, DIN] @ W[DIN, DOUT]   (relu fused on load)
// 64-row x DOUT-col block, 256 threads, TMxTN register tile, H staged
// transposed [kk][row] so a-fragments are a single vector LDS.
// ---------------------------------------------------------------------------
template <int DIN, int DOUT, bool RELU>
__global__ void __launch_bounds__(256, 3) gemm_kernel(const float* __restrict__ H,
                                                      const float* __restrict__ W,
                                                      float* __restrict__ C, int N) {
    constexpr int KB = 32;
    constexpr int TN = (DOUT >= 128) ? 8 : 4;
    constexpr int NC = DOUT / TN;       // col groups: 16 / 16 / 8
    constexpr int NR = 256 / NC;        // row groups: 16 / 16 / 32
    constexpr int TM = 64 / NR;         // rows/thread: 4 / 4 / 2
    constexpr int HSS = 68;             // padded transpose stride (bank-safe, 16B-aligned)

    __shared__ float Hs[KB * HSS];      // [kk][row]
    __shared__ float Ws[KB * DOUT];     // [kk][col]

    const int tid  = threadIdx.x;
    const int row0 = blockIdx.x * 64;
    const int cg   = tid % NC;
    const int rg   = tid / NC;

    float acc[TM][TN];
#pragma unroll
    for (int i = 0; i < TM; i++)
#pragma unroll
        for (int j = 0; j < TN; j++) acc[i][j] = 0.f;

#pragma unroll
    for (int k0 = 0; k0 < DIN; k0 += KB) {
        // stage H (transposed): 64 rows x KB cols
#pragma unroll
        for (int t = tid; t < 64 * KB / 4; t += 256) {
            int r   = t >> 3;           // KB/4 = 8 float4 per row
            int kk4 = t & 7;
            int row = row0 + r;
            float4 v = make_float4(0.f, 0.f, 0.f, 0.f);
            if (row < N)
                v = *(const float4*)(H + (size_t)row * DIN + k0 + kk4 * 4);
            if (RELU) {
                v.x = fmaxf(v.x, 0.f); v.y = fmaxf(v.y, 0.f);
                v.z = fmaxf(v.z, 0.f); v.w = fmaxf(v.w, 0.f);
            }
            Hs[(kk4 * 4 + 0) * HSS + r] = v.x;
            Hs[(kk4 * 4 + 1) * HSS + r] = v.y;
            Hs[(kk4 * 4 + 2) * HSS + r] = v.z;
            Hs[(kk4 * 4 + 3) * HSS + r] = v.w;
        }
        // stage W: KB rows x DOUT cols
#pragma unroll
        for (int t = tid; t < KB * DOUT / 4; t += 256) {
            int kk = t / (DOUT / 4);
            int c4 = t % (DOUT / 4);
            *(float4*)(Ws + kk * DOUT + c4 * 4) =
                *(const float4*)(W + (size_t)(k0 + kk) * DOUT + c4 * 4);
        }
        __syncthreads();

#pragma unroll
        for (int kk = 0; kk < KB; kk++) {
            float a[TM];
            if (TM == 4) {
                float4 av = *(const float4*)(Hs + kk * HSS + rg * 4);
                a[0] = av.x; a[1] = av.y; a[2] = av.z; a[3] = av.w;
            } else {
                float2 av = *(const float2*)(Hs + kk * HSS + rg * 2);
                a[0] = av.x; a[1] = av.y;
            }
            float b[TN];
            {
                float4 b0 = *(const float4*)(Ws + kk * DOUT + cg * TN);
                b[0] = b0.x; b[1] = b0.y; b[2] = b0.z; b[3] = b0.w;
                if (TN == 8) {
                    float4 b1 = *(const float4*)(Ws + kk * DOUT + cg * TN + 4);
                    b[4] = b1.x; b[5] = b1.y; b[6] = b1.z; b[7] = b1.w;
                }
            }
#pragma unroll
            for (int i = 0; i < TM; i++)
#pragma unroll
                for (int j = 0; j < TN; j++)
                    acc[i][j] += a[i] * b[j];
        }
        __syncthreads();
    }

#pragma unroll
    for (int i = 0; i < TM; i++) {
        int row = row0 + rg * TM + i;
        if (row < N) {
            float* dst = C + (size_t)row * DOUT + cg * TN;
            *(float4*)dst = make_float4(acc[i][0], acc[i][1], acc[i][2], acc[i][3]);
            if (TN == 8)
                *(float4*)(dst + 4) = make_float4(acc[i][4], acc[i][5], acc[i][6], acc[i][7]);
        }
    }
}

// ---------------------------------------------------------------------------
// Counting sort by dst: histogram -> hierarchical exclusive scan -> permute
// ---------------------------------------------------------------------------
__global__ void hist_kernel(const int* __restrict__ dst, int* __restrict__ cnt, int E) {
    int e = blockIdx.x * blockDim.x + threadIdx.x;
    if (e < E) atomicAdd(&cnt[dst[e]], 1);
}

// Per-block exclusive scan over SCAN_B counts; local prefixes -> off[],
// block total -> part[blockIdx]. Second-level scan runs on a FULL warp
// (all 32 lanes execute every __shfl_up_sync; inactive tail contributes 0).
__global__ void __launch_bounds__(SCAN_B) scan_block_kernel(const int* __restrict__ cnt,
                                                            int* __restrict__ off,
                                                            int* __restrict__ part, int n) {
    constexpr int NW = SCAN_B / 32;
    __shared__ int wsum[NW];
    int tid = threadIdx.x;
    int i = blockIdx.x * SCAN_B + tid;
    int v = (i < n) ? cnt[i] : 0;
    int x = v;
#pragma unroll
    for (int o = 1; o < 32; o <<= 1) {
        int y = __shfl_up_sync(0xffffffffu, x, o);
        if ((tid & 31) >= o) x += y;
    }
    if ((tid & 31) == 31) wsum[tid >> 5] = x;
    __syncthreads();
    if (tid < 32) {                      // full warp participates
        int w = (tid < NW) ? wsum[tid] : 0;
#pragma unroll
        for (int o = 1; o < 32; o <<= 1) {
            int y = __shfl_up_sync(0xffffffffu, w, o);
            if (tid >= o) w += y;
        }
        if (tid < NW) wsum[tid] = w;
    }
    __syncthreads();
    int excl = x - v + ((tid >= 32) ? wsum[(tid >> 5) - 1] : 0);
    if (i < n) off[i] = excl;
    if (tid == SCAN_B - 1) part[blockIdx.x] = excl + v;
}

// Single block scans the block partials (m <= SCAN_B) in place (exclusive).
__global__ void __launch_bounds__(SCAN_B) scan_part_kernel(int* __restrict__ part, int m) {
    constexpr int NW = SCAN_B / 32;
    __shared__ int wsum[NW];
    int tid = threadIdx.x;
    int v = (tid < m) ? part[tid] : 0;
    int x = v;
#pragma unroll
    for (int o = 1; o < 32; o <<= 1) {
        int y = __shfl_up_sync(0xffffffffu, x, o);
        if ((tid & 31) >= o) x += y;
    }
    if ((tid & 31) == 31) wsum[tid >> 5] = x;
    __syncthreads();
    if (tid < 32) {                      // full warp participates
        int w = (tid < NW) ? wsum[tid] : 0;
#pragma unroll
        for (int o = 1; o < 32; o <<= 1) {
            int y = __shfl_up_sync(0xffffffffu, w, o);
            if (tid >= o) w += y;
        }
        if (tid < NW) wsum[tid] = w;
    }
    __syncthreads();
    int excl = x - v + ((tid >= 32) ? wsum[(tid >> 5) - 1] : 0);
    if (tid < m) part[tid] = excl;
}

// off[i] += part[block]; cur mirrors off; off[n] = E.
__global__ void finalize_scan_kernel(int* __restrict__ off, const int* __restrict__ part,
                                     int* __restrict__ cur, int n, int total) {
    int i = blockIdx.x * blockDim.x + threadIdx.x;
    if (i < n) {
        int o = off[i] + part[blockIdx.x];
        off[i] = o;
        cur[i] = o;
    }
    if (i == 0) off[n] = total;
}

__global__ void permute_kernel(const int* __restrict__ src, const int* __restrict__ dst,
                               const float* __restrict__ val, int* __restrict__ cur,
                               int* __restrict__ src_s, float* __restrict__ val_s, int E) {
    int e = blockIdx.x * blockDim.x + threadIdx.x;
    if (e >= E) return;
    int d = dst[e];
    int pos = atomicAdd(&cur[d], 1);
    src_s[pos] = src[e];
    val_s[pos] = val[e];
}

// ---------------------------------------------------------------------------
// Atomic-free aggregation: out[n] = bias + sum_j S[src_s[j]] * val_s[j]
// ---------------------------------------------------------------------------
template <int D>
__global__ void __launch_bounds__(256) agg_kernel(const float* __restrict__ S,
                                                  const int* __restrict__ off,
                                                  const int* __restrict__ src_s,
                                                  const float* __restrict__ val_s,
                                                  const float* __restrict__ bias,
                                                  float* __restrict__ out, int N) {
    constexpr int L = D / 4;
    int t = blockIdx.x * blockDim.x + threadIdx.x;
    int node = t / L;
    int lane = t % L;
    if (node >= N) return;

    int beg = __ldg(off + node);
    int end = __ldg(off + node + 1);
    float4 acc = ((const float4*)bias)[lane];

    int j = beg;
    for (; j + 2 <= end; j += 2) {
        int   s0 = __ldg(src_s + j);
        int   s1 = __ldg(src_s + j + 1);
        float v0 = __ldg(val_s + j);
        float v1 = __ldg(val_s + j + 1);
        float4 m0 = *(const float4*)(S + (size_t)s0 * D + lane * 4);
        float4 m1 = *(const float4*)(S + (size_t)s1 * D + lane * 4);
        acc.x += v0 * m0.x; acc.y += v0 * m0.y; acc.z += v0 * m0.z; acc.w += v0 * m0.w;
        acc.x += v1 * m1.x; acc.y += v1 * m1.y; acc.z += v1 * m1.z; acc.w += v1 * m1.w;
    }
    if (j < end) {
        int   s0 = __ldg(src_s + j);
        float v0 = __ldg(val_s + j);
        float4 m0 = *(const float4*)(S + (size_t)s0 * D + lane * 4);
        acc.x += v0 * m0.x; acc.y += v0 * m0.y; acc.z += v0 * m0.z; acc.w += v0 * m0.w;
    }

    *(float4*)(out + (size_t)node * D + lane * 4) = acc;
}

// ---------------------------------------------------------------------------
// Launch
// ---------------------------------------------------------------------------
extern "C" void kernel_launch(void* const* d_in, const int* in_sizes, int n_in,
                              void* d_out, int out_size) {
    const float* x    = (const float*)d_in[0];
    const int*   esrc = (const int*)d_in[1];
    const int*   edst = (const int*)d_in[2];
    const float* eval = (const float*)d_in[3];
    const float* W1 = (const float*)d_in[4];
    const float* b1 = (const float*)d_in[5];
    const float* W2 = (const float*)d_in[6];
    const float* b2 = (const float*)d_in[7];
    const float* W3 = (const float*)d_in[8];
    const float* b3 = (const float*)d_in[9];
    const float* W4 = (const float*)d_in[10];
    const float* b4 = (const float*)d_in[11];
    float* out = (float*)d_out;

    float *S = nullptr, *A = nullptr;
    int *off = nullptr, *cur = nullptr, *part = nullptr, *src_s = nullptr;
    float *val_s = nullptr;
    cudaGetSymbolAddress((void**)&S, g_S);
    cudaGetSymbolAddress((void**)&A, g_A);
    cudaGetSymbolAddress((void**)&off, g_off);
    cudaGetSymbolAddress((void**)&cur, g_cur);
    cudaGetSymbolAddress((void**)&part, g_part);
    cudaGetSymbolAddress((void**)&src_s, g_src_s);
    cudaGetSymbolAddress((void**)&val_s, g_val_s);

    const int N = N_NODES;
    const int E = N_EDGES;
    const int gemm_grid = (N + 63) / 64;

    // ---- Build CSR by dst (once; reused by all 4 layers) ----
    cudaMemsetAsync(cur, 0, N * sizeof(int));
    hist_kernel<<<(E + 255) / 256, 256>>>(edst, cur, E);
    scan_block_kernel<<<SCAN_NB, SCAN_B>>>(cur, off, part, N);
    scan_part_kernel<<<1, SCAN_B>>>(part, SCAN_NB);
    finalize_scan_kernel<<<SCAN_NB, SCAN_B>>>(off, part, cur, N, E);
    permute_kernel<<<(E + 255) / 256, 256>>>(esrc, edst, eval, cur, src_s, val_s, E);

    // ---- Layer 1: x(128) -> 128
    gemm_kernel<128, 128, false><<<gemm_grid, 256>>>(x, W1, S, N);
    agg_kernel<128><<<(N * 32 + 255) / 256, 256>>>(S, off, src_s, val_s, b1, A, N);

    // ---- Layer 2: relu(A)(128) -> 128
    gemm_kernel<128, 128, true><<<gemm_grid, 256>>>(A, W2, S, N);
    agg_kernel<128><<<(N * 32 + 255) / 256, 256>>>(S, off, src_s, val_s, b2, A, N);

    // ---- Layer 3: relu(A)(128) -> 64
    gemm_kernel<128, 64, true><<<gemm_grid, 256>>>(A, W3, S, N);
    agg_kernel<64><<<(N * 16 + 255) / 256, 256>>>(S, off, src_s, val_s, b3, A, N);

    // ---- Layer 4: relu(A)(64) -> 32, aggregate directly into d_out
    gemm_kernel<64, 32, true><<<gemm_grid, 256>>>(A, W4, S, N);
    agg_kernel<32><<<(N * 8 + 255) / 256, 256>>>(S, off, src_s, val_s, b4, out, N);
}

// round 7
// speedup vs baseline: 1.2629x; 1.2629x over previous
#include <cuda_runtime.h>
#include <cuda_bf16.h>
#include <cstdint>
#include <cstddef>

#define N_NODES 50000
#define N_EDGES 800000
#define SCAN_B  256
#define SCAN_NB ((N_NODES + SCAN_B - 1) / SCAN_B)

// Scratch (allocation-free rule: __device__ globals)
__device__ float g_S[(size_t)N_NODES * 128];   // support = h @ W
__device__ float g_A[(size_t)N_NODES * 128];   // aggregation target / next-layer input
__device__ int   g_off[N_NODES + 1];           // CSR row offsets (by dst)
__device__ int   g_cur[N_NODES];               // histogram counts / running cursors
__device__ int   g_part[SCAN_NB];              // scan block partials
__device__ int   g_src_s[N_EDGES];             // src sorted by dst
__device__ float g_val_s[N_EDGES];             // val sorted by dst

// ---------------------------------------------------------------------------
// GEMM (round-4 version, measured 46.6us for 128x128):
// C[N, DOUT] = act(H)[N, DIN] @ W[DIN, DOUT], relu fused on load.
// 64 rows/block, 256 threads, K-tiled smem staging, RPTx4 register tile.
// ---------------------------------------------------------------------------
template <int DIN, int DOUT, bool RELU>
__global__ void __launch_bounds__(256) gemm_kernel(const float* __restrict__ H,
                                                   const float* __restrict__ W,
                                                   float* __restrict__ C, int N) {
    constexpr int KB  = 32;
    constexpr int NC  = DOUT / 4;   // column groups (4 cols each)
    constexpr int NR  = 256 / NC;   // row groups
    constexpr int RPT = 64 / NR;    // rows per thread

    __shared__ float Hs[64 * KB];
    __shared__ float Ws[KB * DOUT];

    const int tid  = threadIdx.x;
    const int row0 = blockIdx.x * 64;
    const int cg   = tid % NC;
    const int rg   = tid / NC;

    float acc[RPT][4];
#pragma unroll
    for (int i = 0; i < RPT; i++) {
        acc[i][0] = 0.f; acc[i][1] = 0.f; acc[i][2] = 0.f; acc[i][3] = 0.f;
    }

    for (int k0 = 0; k0 < DIN; k0 += KB) {
#pragma unroll
        for (int t = tid; t < 64 * KB / 4; t += 256) {
            int r   = t >> 3;       // KB/4 = 8 float4 per row
            int kk4 = t & 7;
            int row = row0 + r;
            float4 v = make_float4(0.f, 0.f, 0.f, 0.f);
            if (row < N)
                v = *(const float4*)(H + (size_t)row * DIN + k0 + kk4 * 4);
            if (RELU) {
                v.x = fmaxf(v.x, 0.f); v.y = fmaxf(v.y, 0.f);
                v.z = fmaxf(v.z, 0.f); v.w = fmaxf(v.w, 0.f);
            }
            *(float4*)(Hs + r * KB + kk4 * 4) = v;
        }
#pragma unroll
        for (int t = tid; t < KB * NC; t += 256) {
            int kk = t / NC;
            int c4 = t % NC;
            *(float4*)(Ws + kk * DOUT + c4 * 4) =
                *(const float4*)(W + (size_t)(k0 + kk) * DOUT + c4 * 4);
        }
        __syncthreads();

#pragma unroll
        for (int kk = 0; kk < KB; kk++) {
            float4 b = *(const float4*)(Ws + kk * DOUT + cg * 4);
#pragma unroll
            for (int i = 0; i < RPT; i++) {
                float a = Hs[(rg * RPT + i) * KB + kk];
                acc[i][0] += a * b.x;
                acc[i][1] += a * b.y;
                acc[i][2] += a * b.z;
                acc[i][3] += a * b.w;
            }
        }
        __syncthreads();
    }

#pragma unroll
    for (int i = 0; i < RPT; i++) {
        int row = row0 + rg * RPT + i;
        if (row < N) {
            *(float4*)(C + (size_t)row * DOUT + cg * 4) =
                make_float4(acc[i][0], acc[i][1], acc[i][2], acc[i][3]);
        }
    }
}

// ---------------------------------------------------------------------------
// Counting sort by dst: histogram -> hierarchical exclusive scan -> permute
// ---------------------------------------------------------------------------
__global__ void hist_kernel(const int* __restrict__ dst, int* __restrict__ cnt, int E) {
    int e = blockIdx.x * blockDim.x + threadIdx.x;
    if (e < E) atomicAdd(&cnt[dst[e]], 1);
}

// Per-block exclusive scan over SCAN_B counts; local prefixes -> off[],
// block total -> part[blockIdx]. Second-level scan on a FULL warp.
__global__ void __launch_bounds__(SCAN_B) scan_block_kernel(const int* __restrict__ cnt,
                                                            int* __restrict__ off,
                                                            int* __restrict__ part, int n) {
    constexpr int NW = SCAN_B / 32;
    __shared__ int wsum[NW];
    int tid = threadIdx.x;
    int i = blockIdx.x * SCAN_B + tid;
    int v = (i < n) ? cnt[i] : 0;
    int x = v;
#pragma unroll
    for (int o = 1; o < 32; o <<= 1) {
        int y = __shfl_up_sync(0xffffffffu, x, o);
        if ((tid & 31) >= o) x += y;
    }
    if ((tid & 31) == 31) wsum[tid >> 5] = x;
    __syncthreads();
    if (tid < 32) {                      // full warp participates
        int w = (tid < NW) ? wsum[tid] : 0;
#pragma unroll
        for (int o = 1; o < 32; o <<= 1) {
            int y = __shfl_up_sync(0xffffffffu, w, o);
            if (tid >= o) w += y;
        }
        if (tid < NW) wsum[tid] = w;
    }
    __syncthreads();
    int excl = x - v + ((tid >= 32) ? wsum[(tid >> 5) - 1] : 0);
    if (i < n) off[i] = excl;
    if (tid == SCAN_B - 1) part[blockIdx.x] = excl + v;
}

// Single block scans the block partials (m <= SCAN_B) in place (exclusive).
__global__ void __launch_bounds__(SCAN_B) scan_part_kernel(int* __restrict__ part, int m) {
    constexpr int NW = SCAN_B / 32;
    __shared__ int wsum[NW];
    int tid = threadIdx.x;
    int v = (tid < m) ? part[tid] : 0;
    int x = v;
#pragma unroll
    for (int o = 1; o < 32; o <<= 1) {
        int y = __shfl_up_sync(0xffffffffu, x, o);
        if ((tid & 31) >= o) x += y;
    }
    if ((tid & 31) == 31) wsum[tid >> 5] = x;
    __syncthreads();
    if (tid < 32) {                      // full warp participates
        int w = (tid < NW) ? wsum[tid] : 0;
#pragma unroll
        for (int o = 1; o < 32; o <<= 1) {
            int y = __shfl_up_sync(0xffffffffu, w, o);
            if (tid >= o) w += y;
        }
        if (tid < NW) wsum[tid] = w;
    }
    __syncthreads();
    int excl = x - v + ((tid >= 32) ? wsum[(tid >> 5) - 1] : 0);
    if (tid < m) part[tid] = excl;
}

// off[i] += part[block]; cur mirrors off; off[n] = E.
__global__ void finalize_scan_kernel(int* __restrict__ off, const int* __restrict__ part,
                                     int* __restrict__ cur, int n, int total) {
    int i = blockIdx.x * blockDim.x + threadIdx.x;
    if (i < n) {
        int o = off[i] + part[blockIdx.x];
        off[i] = o;
        cur[i] = o;
    }
    if (i == 0) off[n] = total;
}

__global__ void permute_kernel(const int* __restrict__ src, const int* __restrict__ dst,
                               const float* __restrict__ val, int* __restrict__ cur,
                               int* __restrict__ src_s, float* __restrict__ val_s, int E) {
    int e = blockIdx.x * blockDim.x + threadIdx.x;
    if (e >= E) return;
    int d = dst[e];
    int pos = atomicAdd(&cur[d], 1);
    src_s[pos] = src[e];
    val_s[pos] = val[e];
}

// ---------------------------------------------------------------------------
// Atomic-free aggregation: out[n] = bias + sum_j S[src_s[j]] * val_s[j]
// ---------------------------------------------------------------------------
template <int D>
__global__ void __launch_bounds__(256) agg_kernel(const float* __restrict__ S,
                                                  const int* __restrict__ off,
                                                  const int* __restrict__ src_s,
                                                  const float* __restrict__ val_s,
                                                  const float* __restrict__ bias,
                                                  float* __restrict__ out, int N) {
    constexpr int L = D / 4;
    int t = blockIdx.x * blockDim.x + threadIdx.x;
    int node = t / L;
    int lane = t % L;
    if (node >= N) return;

    int beg = __ldg(off + node);
    int end = __ldg(off + node + 1);
    float4 acc = ((const float4*)bias)[lane];

    int j = beg;
    for (; j + 2 <= end; j += 2) {
        int   s0 = __ldg(src_s + j);
        int   s1 = __ldg(src_s + j + 1);
        float v0 = __ldg(val_s + j);
        float v1 = __ldg(val_s + j + 1);
        float4 m0 = *(const float4*)(S + (size_t)s0 * D + lane * 4);
        float4 m1 = *(const float4*)(S + (size_t)s1 * D + lane * 4);
        acc.x += v0 * m0.x; acc.y += v0 * m0.y; acc.z += v0 * m0.z; acc.w += v0 * m0.w;
        acc.x += v1 * m1.x; acc.y += v1 * m1.y; acc.z += v1 * m1.z; acc.w += v1 * m1.w;
    }
    if (j < end) {
        int   s0 = __ldg(src_s + j);
        float v0 = __ldg(val_s + j);
        float4 m0 = *(const float4*)(S + (size_t)s0 * D + lane * 4);
        acc.x += v0 * m0.x; acc.y += v0 * m0.y; acc.z += v0 * m0.z; acc.w += v0 * m0.w;
    }

    *(float4*)(out + (size_t)node * D + lane * 4) = acc;
}

// ---------------------------------------------------------------------------
// Launch: CSR build forked onto a side stream, overlapping the layer-1 GEMM.
// ---------------------------------------------------------------------------
extern "C" void kernel_launch(void* const* d_in, const int* in_sizes, int n_in,
                              void* d_out, int out_size) {
    const float* x    = (const float*)d_in[0];
    const int*   esrc = (const int*)d_in[1];
    const int*   edst = (const int*)d_in[2];
    const float* eval = (const float*)d_in[3];
    const float* W1 = (const float*)d_in[4];
    const float* b1 = (const float*)d_in[5];
    const float* W2 = (const float*)d_in[6];
    const float* b2 = (const float*)d_in[7];
    const float* W3 = (const float*)d_in[8];
    const float* b3 = (const float*)d_in[9];
    const float* W4 = (const float*)d_in[10];
    const float* b4 = (const float*)d_in[11];
    float* out = (float*)d_out;

    float *S = nullptr, *A = nullptr;
    int *off = nullptr, *cur = nullptr, *part = nullptr, *src_s = nullptr;
    float *val_s = nullptr;
    cudaGetSymbolAddress((void**)&S, g_S);
    cudaGetSymbolAddress((void**)&A, g_A);
    cudaGetSymbolAddress((void**)&off, g_off);
    cudaGetSymbolAddress((void**)&cur, g_cur);
    cudaGetSymbolAddress((void**)&part, g_part);
    cudaGetSymbolAddress((void**)&src_s, g_src_s);
    cudaGetSymbolAddress((void**)&val_s, g_val_s);

    // Persistent side stream + events (created once; no device memory involved).
    static cudaStream_t s_side = nullptr;
    static cudaEvent_t  ev_fork = nullptr, ev_join = nullptr;
    if (s_side == nullptr) {
        cudaStreamCreateWithFlags(&s_side, cudaStreamNonBlocking);
        cudaEventCreateWithFlags(&ev_fork, cudaEventDisableTiming);
        cudaEventCreateWithFlags(&ev_join, cudaEventDisableTiming);
    }

    const int N = N_NODES;
    const int E = N_EDGES;
    const int gemm_grid = (N + 63) / 64;

    // ---- Fork: CSR build on side stream, concurrent with layer-1 GEMM ----
    cudaEventRecord(ev_fork, 0);
    cudaStreamWaitEvent(s_side, ev_fork, 0);

    cudaMemsetAsync(cur, 0, N * sizeof(int), s_side);
    hist_kernel<<<(E + 255) / 256, 256, 0, s_side>>>(edst, cur, E);
    scan_block_kernel<<<SCAN_NB, SCAN_B, 0, s_side>>>(cur, off, part, N);
    scan_part_kernel<<<1, SCAN_B, 0, s_side>>>(part, SCAN_NB);
    finalize_scan_kernel<<<SCAN_NB, SCAN_B, 0, s_side>>>(off, part, cur, N, E);
    permute_kernel<<<(E + 255) / 256, 256, 0, s_side>>>(esrc, edst, eval, cur, src_s, val_s, E);
    cudaEventRecord(ev_join, s_side);

    // ---- Layer 1 GEMM on main stream (overlaps CSR build) ----
    gemm_kernel<128, 128, false><<<gemm_grid, 256>>>(x, W1, S, N);

    // ---- Join: aggregation needs both GEMM-1 and the CSR ----
    cudaStreamWaitEvent(0, ev_join, 0);
    agg_kernel<128><<<(N * 32 + 255) / 256, 256>>>(S, off, src_s, val_s, b1, A, N);

    // ---- Layer 2: relu(A)(128) -> 128
    gemm_kernel<128, 128, true><<<gemm_grid, 256>>>(A, W2, S, N);
    agg_kernel<128><<<(N * 32 + 255) / 256, 256>>>(S, off, src_s, val_s, b2, A, N);

    // ---- Layer 3: relu(A)(128) -> 64
    gemm_kernel<128, 64, true><<<gemm_grid, 256>>>(A, W3, S, N);
    agg_kernel<64><<<(N * 16 + 255) / 256, 256>>>(S, off, src_s, val_s, b3, A, N);

    // ---- Layer 4: relu(A)(64) -> 32, aggregate directly into d_out
    gemm_kernel<64, 32, true><<<gemm_grid, 256>>>(A, W4, S, N);
    agg_kernel<32><<<(N * 8 + 255) / 256, 256>>>(S, off, src_s, val_s, b4, out, N);
}